// round 2
// baseline (speedup 1.0000x reference)
#include <cuda_runtime.h>
#include <cuda_bf16.h>
#include <cstdint>

#define BDIM 32
#define CDIM 512
#define KDIM 32
#define NPIX 4096   // 64*64

// w scratch: [B][K][N] fp32 = 16 MiB
__device__ float g_w[BDIM * KDIM * NPIX];

// ---------- packed fp32x2 helpers ----------
__device__ __forceinline__ unsigned long long fma2(unsigned long long a,
                                                   unsigned long long b,
                                                   unsigned long long c) {
    unsigned long long d;
    asm("fma.rn.f32x2 %0, %1, %2, %3;" : "=l"(d) : "l"(a), "l"(b), "l"(c));
    return d;
}
__device__ __forceinline__ unsigned long long pk(float lo, float hi) {
    unsigned long long r;
    asm("mov.b64 %0, {%1, %2};" : "=l"(r) : "f"(lo), "f"(hi));
    return r;
}
__device__ __forceinline__ float2 upk(unsigned long long v) {
    float2 r;
    asm("mov.b64 {%0, %1}, %2;" : "=f"(r.x), "=f"(r.y) : "l"(v));
    return r;
}

// ============================================================================
// Kernel 1: fused xc-GEMM + x2 + softmax -> w[b][k][n]
// grid (16, 32): blockIdx.x = n-chunk of 256 pixels, blockIdx.y = b
// 256 threads, 1 pixel/thread, f32x2 over C.
// dynamic smem: codewords [32][512] fp32 = 64 KB
// ============================================================================
__global__ __launch_bounds__(256) void enc_k1(
    const float* __restrict__ x,
    const float* __restrict__ cw,
    const float* __restrict__ scale)
{
    extern __shared__ float cw_s[];      // [KDIM][CDIM]
    __shared__ float sc_s[KDIM];
    __shared__ float c2_s[KDIM];
    __shared__ float part[256];

    const int t  = threadIdx.x;
    const int b  = blockIdx.y;
    const int n  = blockIdx.x * 256 + t;

    // stage codewords (64 KB) via float4
    for (int i = t; i < KDIM * CDIM / 4; i += 256)
        ((float4*)cw_s)[i] = ((const float4*)cw)[i];
    if (t < KDIM) sc_s[t] = scale[t];
    __syncthreads();

    // c2[k] = sum_c cw^2 : 8 threads per k, 64 c each
    {
        const int k = t >> 3, off = (t & 7) * 64;
        float s = 0.f;
        #pragma unroll 8
        for (int c = 0; c < 64; ++c) {
            float v = cw_s[k * CDIM + off + c];
            s = fmaf(v, v, s);
        }
        part[t] = s;
        __syncthreads();
        if (t < KDIM) {
            float s2 = 0.f;
            #pragma unroll
            for (int j = 0; j < 8; ++j) s2 += part[t * 8 + j];
            c2_s[t] = s2;
        }
        __syncthreads();
    }

    const float* xp = x + (size_t)b * CDIM * NPIX + n;

    unsigned long long acc[KDIM];
    #pragma unroll
    for (int k = 0; k < KDIM; ++k) acc[k] = 0ull;
    unsigned long long x2a = 0ull;

    // prefetch first c-block
    float nx0 = xp[0];
    float nx1 = xp[(size_t)1 * NPIX];
    float nx2 = xp[(size_t)2 * NPIX];
    float nx3 = xp[(size_t)3 * NPIX];

    #pragma unroll 2
    for (int c = 0; c < CDIM; c += 4) {
        const float xv0 = nx0, xv1 = nx1, xv2 = nx2, xv3 = nx3;
        if (c + 4 < CDIM) {
            const float* q = xp + (size_t)(c + 4) * NPIX;
            nx0 = q[0];
            nx1 = q[(size_t)1 * NPIX];
            nx2 = q[(size_t)2 * NPIX];
            nx3 = q[(size_t)3 * NPIX];
        }
        const unsigned long long xa = pk(xv0, xv1);
        const unsigned long long xb = pk(xv2, xv3);
        x2a = fma2(xa, xa, x2a);
        x2a = fma2(xb, xb, x2a);
        #pragma unroll
        for (int k = 0; k < KDIM; ++k) {
            ulonglong2 cv = *(const ulonglong2*)(cw_s + k * CDIM + c);
            acc[k] = fma2(xa, cv.x, acc[k]);
            acc[k] = fma2(xb, cv.y, acc[k]);
        }
    }

    float2 x2p = upk(x2a);
    const float x2 = x2p.x + x2p.y;

    // dist + softmax over K=32
    float d[KDIM];
    float m = -1e30f;
    #pragma unroll
    for (int k = 0; k < KDIM; ++k) {
        float2 a = upk(acc[k]);
        float xc = a.x + a.y;
        float dist = sc_s[k] * (x2 - 2.0f * xc + c2_s[k]);
        d[k] = dist;
        m = fmaxf(m, dist);
    }
    float sum = 0.f;
    #pragma unroll
    for (int k = 0; k < KDIM; ++k) {
        float e = __expf(d[k] - m);
        d[k] = e;
        sum += e;
    }
    const float inv = 1.0f / sum;

    float* wb = g_w + (size_t)b * KDIM * NPIX + n;
    #pragma unroll
    for (int k = 0; k < KDIM; ++k)
        wb[(size_t)k * NPIX] = d[k] * inv;
}

// ============================================================================
// Kernel 2: out[b][k][c] = sum_n w[b][k][n] * x[b][c][n] - wsum[b][k]*cw[k][c]
// grid (8, 32): blockIdx.x = c-chunk of 64, blockIdx.y = b. 256 threads.
// NT-GEMM: both operands contiguous over n. w staged pre-duplicated {w,w}.
// ============================================================================
__global__ __launch_bounds__(256) void enc_k2(
    const float* __restrict__ x,
    const float* __restrict__ cw,
    float* __restrict__ out)
{
    __shared__ __align__(16) float2 w_s[KDIM][64];   // 16 KB, {w,w} dup
    __shared__ __align__(16) float  x_s[64][66];     // 16.9 KB, [nn][c], pad 66

    const int t  = threadIdx.x;
    const int b  = blockIdx.y;
    const int c0 = blockIdx.x * 64;
    const int tc = t & 31;   // c-pair index (c = c0 + 2*tc)
    const int tk = t >> 5;   // warp id -> k base

    const float* wbase = g_w + (size_t)b * KDIM * NPIX;

    // ---- wsum[k] for this thread's 4 k rows (w is L2-resident) ----
    float wsum[4];
    #pragma unroll
    for (int j = 0; j < 4; ++j) {
        const int k = tk + 8 * j;
        const float4* wr = (const float4*)(wbase + (size_t)k * NPIX);
        float s = 0.f;
        #pragma unroll 4
        for (int i = tc; i < NPIX / 4; i += 32) {
            float4 v = wr[i];
            s += (v.x + v.y) + (v.z + v.w);
        }
        #pragma unroll
        for (int o = 16; o > 0; o >>= 1)
            s += __shfl_xor_sync(0xffffffffu, s, o);
        wsum[j] = s;
    }

    unsigned long long acc[4] = {0ull, 0ull, 0ull, 0ull};

    for (int n0 = 0; n0 < NPIX; n0 += 64) {
        __syncthreads();
        // stage w, duplicated into float2 {v,v}
        #pragma unroll
        for (int i = 0; i < 8; ++i) {
            int idx = t + 256 * i;
            int k = idx >> 6, nn = idx & 63;
            float v = wbase[(size_t)k * NPIX + n0 + nn];
            w_s[k][nn] = make_float2(v, v);
        }
        // stage x tile [nn][ci]
        const float* xb = x + ((size_t)b * CDIM + c0) * NPIX + n0;
        #pragma unroll
        for (int i = 0; i < 16; ++i) {
            int idx = t + 256 * i;
            int ci = idx >> 6, nn = idx & 63;
            x_s[nn][ci] = xb[(size_t)ci * NPIX + nn];
        }
        __syncthreads();

        #pragma unroll 8
        for (int nn = 0; nn < 64; nn += 2) {
            const unsigned long long xp0 =
                *(const unsigned long long*)&x_s[nn][2 * tc];
            const unsigned long long xp1 =
                *(const unsigned long long*)&x_s[nn + 1][2 * tc];
            #pragma unroll
            for (int j = 0; j < 4; ++j) {
                const int k = tk + 8 * j;
                ulonglong2 wd = *(const ulonglong2*)&w_s[k][nn];
                acc[j] = fma2(xp0, wd.x, acc[j]);
                acc[j] = fma2(xp1, wd.y, acc[j]);
            }
        }
    }

    // epilogue: subtract wsum*cw, write coalesced float2
    const int c = c0 + 2 * tc;
    #pragma unroll
    for (int j = 0; j < 4; ++j) {
        const int k = tk + 8 * j;
        float2 a = upk(acc[j]);
        float2 o;
        o.x = a.x - wsum[j] * cw[k * CDIM + c];
        o.y = a.y - wsum[j] * cw[k * CDIM + c + 1];
        *(float2*)&out[((size_t)b * KDIM + k) * CDIM + c] = o;
    }
}

// ============================================================================
extern "C" void kernel_launch(void* const* d_in, const int* in_sizes, int n_in,
                              void* d_out, int out_size)
{
    (void)in_sizes; (void)n_in; (void)out_size;
    const float* x     = (const float*)d_in[0];   // [32,512,64,64]
    const float* cw    = (const float*)d_in[1];   // [32,512]
    const float* scale = (const float*)d_in[2];   // [32]
    float* out = (float*)d_out;                   // [32,32,512]

    cudaFuncSetAttribute(enc_k1, cudaFuncAttributeMaxDynamicSharedMemorySize,
                         KDIM * CDIM * (int)sizeof(float));

    enc_k1<<<dim3(16, 32), 256, KDIM * CDIM * sizeof(float)>>>(x, cw, scale);
    enc_k2<<<dim3(8, 32), 256>>>(x, cw, out);
}

// round 3
// speedup vs baseline: 1.4103x; 1.4103x over previous
#include <cuda_runtime.h>
#include <cuda_bf16.h>
#include <cstdint>

#define BDIM 32
#define CDIM 512
#define KDIM 32
#define NPIX 4096   // 64*64

// scratch: dist -> (in-place) softmax weights, then k2 partials
__device__ float g_w[BDIM * KDIM * NPIX];          // 16 MiB
__device__ float g_part[4 * BDIM * KDIM * CDIM];   // 8 MiB

// ---------- packed fp32x2 helpers ----------
__device__ __forceinline__ unsigned long long fma2(unsigned long long a,
                                                   unsigned long long b,
                                                   unsigned long long c) {
    unsigned long long d;
    asm("fma.rn.f32x2 %0, %1, %2, %3;" : "=l"(d) : "l"(a), "l"(b), "l"(c));
    return d;
}
__device__ __forceinline__ float2 upk(unsigned long long v) {
    float2 r;
    asm("mov.b64 {%0, %1}, %2;" : "=f"(r.x), "=f"(r.y) : "l"(v));
    return r;
}

// ============================================================================
// Kernel 1: dist[b][k][n] = scale_k*(x2 - 2*xc + c2)  (no softmax here)
// grid (16, 32): blockIdx.x = n-tile of 256, blockIdx.y = b. 256 threads.
// CTA tile 256n x 32k, thread tile 8n x 4k.
// lane = kg*8+ng (kg=lane>>3, ng=lane&7); warp = kgp*4+ngp (kgp=w>>2, ngp=w&3)
// thread n: ngp*64 + {4ng..4ng+3} and +32;  thread k: kgp*16 + 4kg + kk
// ============================================================================
__global__ __launch_bounds__(256) void enc_k1(
    const float* __restrict__ x,
    const float* __restrict__ cw,
    const float* __restrict__ scale)
{
    __shared__ __align__(16) float x_s[32 * 256];   // [cb][n] 32 KB
    __shared__ __align__(16) float cwd_s[32 * 68];  // [cb][{v,v}x32k + pad] 8.5 KB
    __shared__ float x2_s[256];
    __shared__ float c2_s[KDIM];
    __shared__ float sc_s[KDIM];

    const int t    = threadIdx.x;
    const int b    = blockIdx.y;
    const int n0   = blockIdx.x * 256;
    const int lane = t & 31, w = t >> 5;
    const int kg = lane >> 3, ng = lane & 7;
    const int kgp = w >> 2,  ngp = w & 3;
    const int nbase = ngp * 64;

    // ---- c2[k] precompute (x2_s used as scratch) ----
    {
        const int k = t >> 3, seg = t & 7;
        const float4* p = (const float4*)(cw + k * CDIM + seg * 64);
        float s = 0.f;
        #pragma unroll
        for (int i = 0; i < 16; ++i) {
            float4 v = p[i];
            s += v.x * v.x + v.y * v.y + v.z * v.z + v.w * v.w;
        }
        x2_s[t] = s;
        if (t < KDIM) sc_s[t] = scale[t];
        __syncthreads();
        if (t < KDIM) {
            float s2 = 0.f;
            #pragma unroll
            for (int j = 0; j < 8; ++j) s2 += x2_s[t * 8 + j];
            c2_s[t] = s2;
        }
    }

    unsigned long long acc[16];
    #pragma unroll
    for (int i = 0; i < 16; ++i) acc[i] = 0ull;
    float x2a = 0.f;

    const float* xb = x + (size_t)b * CDIM * NPIX + n0;

    for (int c0 = 0; c0 < CDIM; c0 += 32) {
        __syncthreads();
        // stage x tile [32c][256n] (direct copy, n contiguous)
        #pragma unroll
        for (int i = 0; i < 8; ++i) {
            int idx = t + 256 * i;
            int cb = idx >> 6, nq = idx & 63;
            float4 v = *(const float4*)(xb + (size_t)(c0 + cb) * NPIX + 4 * nq);
            *(float4*)(x_s + cb * 256 + 4 * nq) = v;
        }
        // stage cw duplicated {v,v}
        {
            int k = t >> 3, cq = t & 7;
            float4 v = *(const float4*)(cw + k * CDIM + c0 + 4 * cq);
            float vv[4] = {v.x, v.y, v.z, v.w};
            #pragma unroll
            for (int j = 0; j < 4; ++j)
                *(float2*)(cwd_s + (4 * cq + j) * 68 + 2 * k) =
                    make_float2(vv[j], vv[j]);
        }
        __syncthreads();

        // x2 partial: thread t owns pixel n=t
        #pragma unroll 8
        for (int cb = 0; cb < 32; ++cb) {
            float v = x_s[cb * 256 + t];
            x2a = fmaf(v, v, x2a);
        }

        // main GEMM chunk
        #pragma unroll 4
        for (int cb = 0; cb < 32; ++cb) {
            ulonglong2 xA = *(const ulonglong2*)(x_s + cb * 256 + nbase + 4 * ng);
            ulonglong2 xB = *(const ulonglong2*)(x_s + cb * 256 + nbase + 32 + 4 * ng);
            ulonglong2 wA = *(const ulonglong2*)(cwd_s + cb * 68 + kgp * 32 + 8 * kg);
            ulonglong2 wB = *(const ulonglong2*)(cwd_s + cb * 68 + kgp * 32 + 8 * kg + 4);
            // kk = 0,1 from wA.{x,y}; kk = 2,3 from wB.{x,y}
            acc[0]  = fma2(xA.x, wA.x, acc[0]);
            acc[1]  = fma2(xA.y, wA.x, acc[1]);
            acc[2]  = fma2(xB.x, wA.x, acc[2]);
            acc[3]  = fma2(xB.y, wA.x, acc[3]);
            acc[4]  = fma2(xA.x, wA.y, acc[4]);
            acc[5]  = fma2(xA.y, wA.y, acc[5]);
            acc[6]  = fma2(xB.x, wA.y, acc[6]);
            acc[7]  = fma2(xB.y, wA.y, acc[7]);
            acc[8]  = fma2(xA.x, wB.x, acc[8]);
            acc[9]  = fma2(xA.y, wB.x, acc[9]);
            acc[10] = fma2(xB.x, wB.x, acc[10]);
            acc[11] = fma2(xB.y, wB.x, acc[11]);
            acc[12] = fma2(xA.x, wB.y, acc[12]);
            acc[13] = fma2(xA.y, wB.y, acc[13]);
            acc[14] = fma2(xB.x, wB.y, acc[14]);
            acc[15] = fma2(xB.y, wB.y, acc[15]);
        }
    }

    __syncthreads();
    x2_s[t] = x2a;
    __syncthreads();

    // epilogue: dist, store to g_w
    float* outb = g_w + (size_t)b * KDIM * NPIX + n0;
    const int nA = nbase + 4 * ng;
    #pragma unroll
    for (int kk = 0; kk < 4; ++kk) {
        const int k = kgp * 16 + 4 * kg + kk;
        const float sck = sc_s[k], c2k = c2_s[k];
        float2 p0 = upk(acc[kk * 4 + 0]);
        float2 p1 = upk(acc[kk * 4 + 1]);
        float2 p2 = upk(acc[kk * 4 + 2]);
        float2 p3 = upk(acc[kk * 4 + 3]);
        float4 dA, dB;
        dA.x = sck * (x2_s[nA + 0] - 2.f * p0.x + c2k);
        dA.y = sck * (x2_s[nA + 1] - 2.f * p0.y + c2k);
        dA.z = sck * (x2_s[nA + 2] - 2.f * p1.x + c2k);
        dA.w = sck * (x2_s[nA + 3] - 2.f * p1.y + c2k);
        dB.x = sck * (x2_s[nA + 32] - 2.f * p2.x + c2k);
        dB.y = sck * (x2_s[nA + 33] - 2.f * p2.y + c2k);
        dB.z = sck * (x2_s[nA + 34] - 2.f * p3.x + c2k);
        dB.w = sck * (x2_s[nA + 35] - 2.f * p3.y + c2k);
        *(float4*)(outb + (size_t)k * NPIX + nA)      = dA;
        *(float4*)(outb + (size_t)k * NPIX + nA + 32) = dB;
    }
}

// ============================================================================
// Kernel 1b: softmax over k (32), in-place on g_w. grid (16,32) x 256.
// ============================================================================
__global__ __launch_bounds__(256) void enc_sm()
{
    const int t = threadIdx.x;
    const int b = blockIdx.y;
    const int n = blockIdx.x * 256 + t;
    float* p = g_w + (size_t)b * KDIM * NPIX + n;
    float v[KDIM];
    #pragma unroll
    for (int k = 0; k < KDIM; ++k) v[k] = p[(size_t)k * NPIX];
    float m = v[0];
    #pragma unroll
    for (int k = 1; k < KDIM; ++k) m = fmaxf(m, v[k]);
    float s = 0.f;
    #pragma unroll
    for (int k = 0; k < KDIM; ++k) { v[k] = __expf(v[k] - m); s += v[k]; }
    const float inv = 1.0f / s;
    #pragma unroll
    for (int k = 0; k < KDIM; ++k) p[(size_t)k * NPIX] = v[k] * inv;
}

// ============================================================================
// Kernel 2: partial wx[s][b][k][c] = sum_{n in slice s} w[k][n]*x[c][n]
// grid (4 csplit, 4 nsplit, 32 b), 256 threads. CTA tile 32k x 128c x 1024n.
// f32x2 packed over n. thread tile 4k x 4c.
// lane = kg*8+cg; warp = kgp*4+cgp.
// thread c: c0 + cgp*32 + 8j + cg (j=0..3);  thread k: kgp*16 + 4kk + kg
// ============================================================================
__global__ __launch_bounds__(256) void enc_k2(const float* __restrict__ x)
{
    __shared__ __align__(16) float x_s[128 * 68];  // [c][n] 34 KB
    __shared__ __align__(16) float w_s[32 * 68];   // [k][n] 8.5 KB

    const int t  = threadIdx.x;
    const int b  = blockIdx.z;
    const int s  = blockIdx.y;
    const int c0 = blockIdx.x * 128;
    const int lane = t & 31, w = t >> 5;
    const int kg = lane >> 3, cg = lane & 7;
    const int kgp = w >> 2,  cgp = w & 3;

    unsigned long long acc[16];
    #pragma unroll
    for (int i = 0; i < 16; ++i) acc[i] = 0ull;

    const float* xb = x + ((size_t)b * CDIM + c0) * NPIX;
    const float* wb = g_w + (size_t)b * KDIM * NPIX;
    const int nb0 = s * 1024;

    for (int nb = nb0; nb < nb0 + 1024; nb += 64) {
        __syncthreads();
        #pragma unroll
        for (int i = 0; i < 8; ++i) {
            int idx = t + 256 * i;
            int cl = idx >> 4, nq = idx & 15;
            float4 v = *(const float4*)(xb + (size_t)cl * NPIX + nb + 4 * nq);
            *(float4*)(x_s + cl * 68 + 4 * nq) = v;
        }
        #pragma unroll
        for (int i = 0; i < 2; ++i) {
            int idx = t + 256 * i;
            int kl = idx >> 4, nq = idx & 15;
            float4 v = *(const float4*)(wb + (size_t)kl * NPIX + nb + 4 * nq);
            *(float4*)(w_s + kl * 68 + 4 * nq) = v;
        }
        __syncthreads();

        #pragma unroll 4
        for (int nn = 0; nn < 64; nn += 4) {
            ulonglong2 xq[4], wq[4];
            #pragma unroll
            for (int j = 0; j < 4; ++j)
                xq[j] = *(const ulonglong2*)(x_s + (cgp * 32 + 8 * j + cg) * 68 + nn);
            #pragma unroll
            for (int kk = 0; kk < 4; ++kk)
                wq[kk] = *(const ulonglong2*)(w_s + (kgp * 16 + 4 * kk + kg) * 68 + nn);
            #pragma unroll
            for (int kk = 0; kk < 4; ++kk) {
                #pragma unroll
                for (int j = 0; j < 4; ++j) {
                    acc[kk * 4 + j] = fma2(xq[j].x, wq[kk].x, acc[kk * 4 + j]);
                    acc[kk * 4 + j] = fma2(xq[j].y, wq[kk].y, acc[kk * 4 + j]);
                }
            }
        }
    }

    // partial store
    #pragma unroll
    for (int kk = 0; kk < 4; ++kk) {
        const int k = kgp * 16 + 4 * kk + kg;
        #pragma unroll
        for (int j = 0; j < 4; ++j) {
            float2 a = upk(acc[kk * 4 + j]);
            const int c = c0 + cgp * 32 + 8 * j + cg;
            g_part[(((size_t)s * BDIM + b) * KDIM + k) * CDIM + c] = a.x + a.y;
        }
    }
}

// ============================================================================
// Kernel 3: out[b][k][c] = sum_s part[s][b][k][c] - wsum[b][k]*cw[k][c]
// grid (32 k, 32 b), 128 threads.
// ============================================================================
__global__ __launch_bounds__(128) void enc_red(const float* __restrict__ cw,
                                               float* __restrict__ out)
{
    __shared__ float red[4];
    const int t = threadIdx.x;
    const int k = blockIdx.x, b = blockIdx.y;

    const float4* wr = (const float4*)(g_w + ((size_t)b * KDIM + k) * NPIX);
    float s = 0.f;
    #pragma unroll
    for (int i = 0; i < 8; ++i) {
        float4 v = wr[t + 128 * i];
        s += (v.x + v.y) + (v.z + v.w);
    }
    #pragma unroll
    for (int o = 16; o > 0; o >>= 1) s += __shfl_xor_sync(0xffffffffu, s, o);
    if ((t & 31) == 0) red[t >> 5] = s;
    __syncthreads();
    const float ws = red[0] + red[1] + red[2] + red[3];

    const int c = 4 * t;
    float4 p = *(const float4*)(g_part + (((size_t)0 * BDIM + b) * KDIM + k) * CDIM + c);
    #pragma unroll
    for (int sp = 1; sp < 4; ++sp) {
        float4 q = *(const float4*)(g_part + (((size_t)sp * BDIM + b) * KDIM + k) * CDIM + c);
        p.x += q.x; p.y += q.y; p.z += q.z; p.w += q.w;
    }
    float4 cv = *(const float4*)(cw + k * CDIM + c);
    float4 o4;
    o4.x = p.x - ws * cv.x;
    o4.y = p.y - ws * cv.y;
    o4.z = p.z - ws * cv.z;
    o4.w = p.w - ws * cv.w;
    *(float4*)(out + ((size_t)b * KDIM + k) * CDIM + c) = o4;
}

// ============================================================================
extern "C" void kernel_launch(void* const* d_in, const int* in_sizes, int n_in,
                              void* d_out, int out_size)
{
    (void)in_sizes; (void)n_in; (void)out_size;
    const float* x     = (const float*)d_in[0];   // [32,512,64,64]
    const float* cw    = (const float*)d_in[1];   // [32,512]
    const float* scale = (const float*)d_in[2];   // [32]
    float* out = (float*)d_out;                   // [32,32,512]

    enc_k1 <<<dim3(16, 32), 256>>>(x, cw, scale);
    enc_sm <<<dim3(16, 32), 256>>>();
    enc_k2 <<<dim3(4, 4, 32), 256>>>(x);
    enc_red<<<dim3(32, 32), 128>>>(cw, out);
}